// round 10
// baseline (speedup 1.0000x reference)
#include <cuda_runtime.h>
#include <math.h>

#define NN 50000
#define NE 800000
#define HD 64
#define COLS 192      // 2 bases * 64 + 64 loop cols
#define TN 64         // nodes per block in node GEMM
#define XS 68         // x smem row stride (floats), float4-aligned

typedef unsigned long long u64;

// Scratch (no allocations allowed)
__device__ __align__(16) float g_proj[NN * 128];   // [n][b][o], b in {0,1}
__device__ __align__(16) float g_agg[NN * HD];     // aggregation / layer output
__device__ float g_partial[512];

// ---- packed f32x2 helpers (FFMA2 — PTX-only on sm_103a) ----------------
__device__ __forceinline__ u64 pack2(float lo, float hi) {
    u64 r; asm("mov.b64 %0, {%1, %2};" : "=l"(r) : "f"(lo), "f"(hi)); return r;
}
__device__ __forceinline__ void unpack2(u64 v, float& lo, float& hi) {
    asm("mov.b64 {%0, %1}, %2;" : "=f"(lo), "=f"(hi) : "l"(v));
}
__device__ __forceinline__ u64 fma2(u64 a, u64 b, u64 c) {
    u64 d; asm("fma.rn.f32x2 %0, %1, %2, %3;" : "=l"(d) : "l"(a), "l"(b), "l"(c));
    return d;
}

// ---------------------------------------------------------------------------
// Node GEMM: out[n, 0:128] = proj (x @ V[b]), out[n,128:192] = x @ loop_w + bias
// x source: layer0 = features input; layer1 = relu(g_agg) read in-place.
// Block: 64 nodes x 192 cols, 256 threads, thread tile 4 nodes x 12 cols,
// accumulated as 4x6 packed f32x2 pairs. (256,3): 85-reg budget, no spill.
// ---------------------------------------------------------------------------
__global__ __launch_bounds__(256, 3) void node_gemm_kernel(
    const float* __restrict__ xin,     // features (used when from_agg==0)
    const float* __restrict__ V,       // [2,64,64] (b,i,o) for this layer
    const float* __restrict__ loopw,   // [64,64] for this layer
    const float* __restrict__ bias,    // [64] for this layer
    int from_agg)
{
    extern __shared__ float sm[];
    float* Wsh = sm;                 // [64][192]
    float* Xsh = sm + 64 * COLS;     // [64][XS]

    const int tid = threadIdx.x;
    const int n0 = blockIdx.x * TN;

    // Load weights into smem: Wsh[k][c]
    for (int idx = tid; idx < 64 * COLS; idx += 256) {
        int k = idx / COLS, c = idx - k * COLS;
        float v;
        if (c < 128) {
            int b = c >> 6, o = c & 63;
            v = V[(b * 64 + k) * 64 + o];
        } else {
            v = loopw[k * 64 + (c - 128)];
        }
        Wsh[k * COLS + c] = v;
    }
    // Load x tile transposed: Xsh[k][n_local]
    for (int idx = tid; idx < TN * 64; idx += 256) {
        int nl = idx >> 6, k = idx & 63;
        int gn = n0 + nl;
        float v = 0.0f;
        if (gn < NN) {
            if (from_agg) {
                v = fmaxf(g_agg[gn * HD + k], 0.0f);
            } else {
                v = xin[gn * HD + k];
            }
        }
        Xsh[k * XS + nl] = v;
    }
    __syncthreads();

    const int cg = tid & 15;     // col group (12 cols = 6 pairs)
    const int ng = tid >> 4;     // node group (4 nodes)
    const int c0 = cg * 12;      // 48B*cg -> 16B aligned

    u64 acc[4][6];
    #pragma unroll
    for (int i = 0; i < 4; i++)
        #pragma unroll
        for (int j = 0; j < 6; j++) acc[i][j] = 0ULL;

    #pragma unroll 4
    for (int k = 0; k < 64; k++) {
        float4 xv = *(const float4*)&Xsh[k * XS + ng * 4];
        ulonglong2 wv0 = *(const ulonglong2*)&Wsh[k * COLS + c0];
        ulonglong2 wv1 = *(const ulonglong2*)&Wsh[k * COLS + c0 + 4];
        ulonglong2 wv2 = *(const ulonglong2*)&Wsh[k * COLS + c0 + 8];
        u64 w[6] = {wv0.x, wv0.y, wv1.x, wv1.y, wv2.x, wv2.y};
        u64 xx[4] = {pack2(xv.x, xv.x), pack2(xv.y, xv.y),
                     pack2(xv.z, xv.z), pack2(xv.w, xv.w)};
        #pragma unroll
        for (int i = 0; i < 4; i++)
            #pragma unroll
            for (int j = 0; j < 6; j++)
                acc[i][j] = fma2(xx[i], w[j], acc[i][j]);
    }

    // Store: cols < 128 -> g_proj; cols >= 128 -> g_agg (self term + bias)
    #pragma unroll
    for (int i = 0; i < 4; i++) {
        int gn = n0 + ng * 4 + i;
        if (gn >= NN) break;
        #pragma unroll
        for (int j = 0; j < 6; j++) {
            float lo, hi;
            unpack2(acc[i][j], lo, hi);
            int c = c0 + j * 2;
            if (c < 128) {
                g_proj[gn * 128 + c]     = lo;
                g_proj[gn * 128 + c + 1] = hi;
            } else {
                g_agg[gn * HD + (c - 128)]     = lo + bias[c - 128];
                g_agg[gn * HD + (c - 128) + 1] = hi + bias[c - 127];
            }
        }
    }
}

// ---------------------------------------------------------------------------
// Edge scatter: msg = c0*proj[src,0,:] + c1*proj[src,1,:]; g_agg[dst] += msg
// 16 lanes per edge (4 floats each), vector reduction red.global.add.v4.f32.
// Block = 256 threads = 16 groups; each group handles 4 consecutive edges.
// __launch_bounds__(256,4): 64-reg budget so the 8 gather LDG.128s can stay
// front-batched in registers (MLP=8). At 32 regs ptxas re-serializes them.
// ---------------------------------------------------------------------------
__global__ __launch_bounds__(256, 4) void edge_kernel(
    const int* __restrict__ src, const int* __restrict__ dst,
    const int* __restrict__ etype,
    const float* __restrict__ comp)   // [8][2] for this layer
{
    const int tid = threadIdx.x;
    const int grp = tid >> 4;
    const int lane = tid & 15;
    const int ebase = blockIdx.x * 64 + grp * 4;

    // Phase 1: all edge metadata
    int s[4], d[4], t[4];
    #pragma unroll
    for (int i = 0; i < 4; i++) {
        s[i] = __ldg(&src[ebase + i]);
        d[i] = __ldg(&dst[ebase + i]);
        t[i] = __ldg(&etype[ebase + i]);
    }
    float c0[4], c1[4];
    #pragma unroll
    for (int i = 0; i < 4; i++) {
        c0[i] = __ldg(&comp[t[i] * 2]);
        c1[i] = __ldg(&comp[t[i] * 2 + 1]);
    }

    // Phase 2: front-batch all 8 gathers (MLP=8), read-only path
    float4 p0[4], p1[4];
    #pragma unroll
    for (int i = 0; i < 4; i++) {
        const float4* p = (const float4*)(g_proj + (size_t)s[i] * 128);
        p0[i] = __ldg(&p[lane]);
        p1[i] = __ldg(&p[lane + 16]);
    }

    // Phase 3: mix + vector reduction
    #pragma unroll
    for (int i = 0; i < 4; i++) {
        float4 m;
        m.x = fmaf(c0[i], p0[i].x, c1[i] * p1[i].x);
        m.y = fmaf(c0[i], p0[i].y, c1[i] * p1[i].y);
        m.z = fmaf(c0[i], p0[i].z, c1[i] * p1[i].z);
        m.w = fmaf(c0[i], p0[i].w, c1[i] * p1[i].w);

        float* a = g_agg + (size_t)d[i] * HD + lane * 4;
        asm volatile("red.global.add.v4.f32 [%0], {%1, %2, %3, %4};"
                     :: "l"(a), "f"(m.x), "f"(m.y), "f"(m.z), "f"(m.w)
                     : "memory");
    }
}

// ---------------------------------------------------------------------------
// Final: sigmoid( sum(g_agg .* fc_w) + fc_b )
// ---------------------------------------------------------------------------
__global__ __launch_bounds__(256) void final_partial_kernel(
    const float* __restrict__ fcw)
{
    __shared__ float red[256];
    const int tid = threadIdx.x;
    const int total4 = NN * HD / 4;   // 800000 float4
    float s = 0.0f;
    for (int i = blockIdx.x * 256 + tid; i < total4; i += gridDim.x * 256) {
        float4 a = ((const float4*)g_agg)[i];
        float4 w = ((const float4*)fcw)[i];
        s += a.x * w.x + a.y * w.y + a.z * w.z + a.w * w.w;
    }
    red[tid] = s;
    __syncthreads();
    #pragma unroll
    for (int off = 128; off > 0; off >>= 1) {
        if (tid < off) red[tid] += red[tid + off];
        __syncthreads();
    }
    if (tid == 0) g_partial[blockIdx.x] = red[0];
}

__global__ void final_out_kernel(const float* __restrict__ fcb,
                                 float* __restrict__ out, int nparts)
{
    __shared__ float red[256];
    const int tid = threadIdx.x;
    float s = 0.0f;
    for (int i = tid; i < nparts; i += 256) s += g_partial[i];
    red[tid] = s;
    __syncthreads();
    #pragma unroll
    for (int off = 128; off > 0; off >>= 1) {
        if (tid < off) red[tid] += red[tid + off];
        __syncthreads();
    }
    if (tid == 0) {
        float v = red[0] + fcb[0];
        out[0] = 1.0f / (1.0f + expf(-v));
    }
}

// ---------------------------------------------------------------------------
extern "C" void kernel_launch(void* const* d_in, const int* in_sizes, int n_in,
                              void* d_out, int out_size)
{
    const float* features = (const float*)d_in[0];   // [50000,64]
    const float* V        = (const float*)d_in[1];   // [2,2,64,64]
    const float* comp     = (const float*)d_in[2];   // [2,8,2]
    const float* loop_w   = (const float*)d_in[3];   // [2,64,64]
    const float* bias     = (const float*)d_in[4];   // [2,64]
    const float* fc_w     = (const float*)d_in[5];   // [1, 50000*64]
    const float* fc_b     = (const float*)d_in[6];   // [1]
    const int*   src      = (const int*)d_in[7];     // [800000]
    const int*   dst      = (const int*)d_in[8];
    const int*   etype    = (const int*)d_in[9];
    float* out = (float*)d_out;

    const int smem_bytes = (64 * COLS + 64 * XS) * (int)sizeof(float); // 66560
    cudaFuncSetAttribute(node_gemm_kernel,
                         cudaFuncAttributeMaxDynamicSharedMemorySize, smem_bytes);

    const int gemm_blocks = (NN + TN - 1) / TN;   // 782
    const int edge_blocks = NE / 64;              // 12500

    // ---- layer 0 ----
    node_gemm_kernel<<<gemm_blocks, 256, smem_bytes>>>(
        features, V + 0 * 2 * 64 * 64, loop_w + 0 * 64 * 64, bias + 0 * 64, 0);
    edge_kernel<<<edge_blocks, 256>>>(src, dst, etype, comp + 0 * 16);

    // ---- layer 1 (x = relu(g_agg), read in-place inside node_gemm) ----
    node_gemm_kernel<<<gemm_blocks, 256, smem_bytes>>>(
        features /*unused*/, V + 1 * 2 * 64 * 64, loop_w + 1 * 64 * 64,
        bias + 1 * 64, 1);
    edge_kernel<<<edge_blocks, 256>>>(src, dst, etype, comp + 1 * 16);

    // ---- final dot + sigmoid ----
    const int red_blocks = 512;
    final_partial_kernel<<<red_blocks, 256>>>(fc_w);
    final_out_kernel<<<1, 256>>>(fc_b, out, red_blocks);
}

// round 13
// speedup vs baseline: 1.1004x; 1.1004x over previous
#include <cuda_runtime.h>
#include <cuda_fp16.h>
#include <math.h>

#define NN 50000
#define NE 800000
#define HD 64
#define COLS 192      // 2 bases * 64 + 64 loop cols
#define TN 64         // nodes per block in node GEMM
#define XS 68         // x smem row stride (floats), float4-aligned

typedef unsigned long long u64;

// Scratch (no allocations allowed)
__device__ __align__(16) __half g_proj[NN * 128];  // fp16: [n][b][o], b in {0,1}
__device__ __align__(16) float g_agg[NN * HD];     // aggregation / layer output
__device__ float g_partial[512];

// ---- packed f32x2 helpers (FFMA2 — PTX-only on sm_103a) ----------------
__device__ __forceinline__ u64 pack2(float lo, float hi) {
    u64 r; asm("mov.b64 %0, {%1, %2};" : "=l"(r) : "f"(lo), "f"(hi)); return r;
}
__device__ __forceinline__ void unpack2(u64 v, float& lo, float& hi) {
    asm("mov.b64 {%0, %1}, %2;" : "=f"(lo), "=f"(hi) : "l"(v));
}
__device__ __forceinline__ u64 fma2(u64 a, u64 b, u64 c) {
    u64 d; asm("fma.rn.f32x2 %0, %1, %2, %3;" : "=l"(d) : "l"(a), "l"(b), "l"(c));
    return d;
}

// ---------------------------------------------------------------------------
// Node GEMM: cols 0:128 -> g_proj (fp16), cols 128:192 -> g_agg = x@loop_w+bias
// x source: layer0 = features input; layer1 = relu(g_agg) read in-place.
// Block: 64 nodes x 192 cols, 256 threads, thread tile 4 nodes x 12 cols,
// accumulated as 4x6 packed f32x2 pairs.
// ---------------------------------------------------------------------------
__global__ __launch_bounds__(256, 3) void node_gemm_kernel(
    const float* __restrict__ xin,     // features (used when from_agg==0)
    const float* __restrict__ V,       // [2,64,64] (b,i,o) for this layer
    const float* __restrict__ loopw,   // [64,64] for this layer
    const float* __restrict__ bias,    // [64] for this layer
    int from_agg)
{
    extern __shared__ float sm[];
    float* Wsh = sm;                 // [64][192]
    float* Xsh = sm + 64 * COLS;     // [64][XS]

    const int tid = threadIdx.x;
    const int n0 = blockIdx.x * TN;

    // Load weights into smem: Wsh[k][c]
    for (int idx = tid; idx < 64 * COLS; idx += 256) {
        int k = idx / COLS, c = idx - k * COLS;
        float v;
        if (c < 128) {
            int b = c >> 6, o = c & 63;
            v = V[(b * 64 + k) * 64 + o];
        } else {
            v = loopw[k * 64 + (c - 128)];
        }
        Wsh[k * COLS + c] = v;
    }
    // Load x tile transposed: Xsh[k][n_local]
    for (int idx = tid; idx < TN * 64; idx += 256) {
        int nl = idx >> 6, k = idx & 63;
        int gn = n0 + nl;
        float v = 0.0f;
        if (gn < NN) {
            if (from_agg) {
                v = fmaxf(g_agg[gn * HD + k], 0.0f);
            } else {
                v = xin[gn * HD + k];
            }
        }
        Xsh[k * XS + nl] = v;
    }
    __syncthreads();

    const int cg = tid & 15;     // col group (12 cols = 6 pairs)
    const int ng = tid >> 4;     // node group (4 nodes)
    const int c0 = cg * 12;      // 48B*cg -> 16B aligned

    u64 acc[4][6];
    #pragma unroll
    for (int i = 0; i < 4; i++)
        #pragma unroll
        for (int j = 0; j < 6; j++) acc[i][j] = 0ULL;

    #pragma unroll 4
    for (int k = 0; k < 64; k++) {
        float4 xv = *(const float4*)&Xsh[k * XS + ng * 4];
        ulonglong2 wv0 = *(const ulonglong2*)&Wsh[k * COLS + c0];
        ulonglong2 wv1 = *(const ulonglong2*)&Wsh[k * COLS + c0 + 4];
        ulonglong2 wv2 = *(const ulonglong2*)&Wsh[k * COLS + c0 + 8];
        u64 w[6] = {wv0.x, wv0.y, wv1.x, wv1.y, wv2.x, wv2.y};
        u64 xx[4] = {pack2(xv.x, xv.x), pack2(xv.y, xv.y),
                     pack2(xv.z, xv.z), pack2(xv.w, xv.w)};
        #pragma unroll
        for (int i = 0; i < 4; i++)
            #pragma unroll
            for (int j = 0; j < 6; j++)
                acc[i][j] = fma2(xx[i], w[j], acc[i][j]);
    }

    // Store: cols < 128 -> g_proj (fp16 pairs); cols >= 128 -> g_agg (+bias)
    #pragma unroll
    for (int i = 0; i < 4; i++) {
        int gn = n0 + ng * 4 + i;
        if (gn >= NN) break;
        #pragma unroll
        for (int j = 0; j < 6; j++) {
            float lo, hi;
            unpack2(acc[i][j], lo, hi);
            int c = c0 + j * 2;
            if (c < 128) {
                *(__half2*)&g_proj[gn * 128 + c] = __floats2half2_rn(lo, hi);
            } else {
                g_agg[gn * HD + (c - 128)]     = lo + bias[c - 128];
                g_agg[gn * HD + (c - 128) + 1] = hi + bias[c - 127];
            }
        }
    }
}

// ---------------------------------------------------------------------------
// Edge scatter: msg = c0*proj[src,0,:] + c1*proj[src,1,:]; g_agg[dst] += msg
// proj is fp16 (256B/row-basis-pair) -> gather bytes halved vs fp32.
// 16 lanes per edge, each lane: 2x LDG.64 (4 halfs each), fp32 math,
// red.global.add.v4.f32 scatter (fp32 accumulation preserved).
// ---------------------------------------------------------------------------
__global__ __launch_bounds__(256, 4) void edge_kernel(
    const int* __restrict__ src, const int* __restrict__ dst,
    const int* __restrict__ etype,
    const float* __restrict__ comp)   // [8][2] for this layer
{
    const int tid = threadIdx.x;
    const int grp = tid >> 4;
    const int lane = tid & 15;
    const int ebase = blockIdx.x * 64 + grp * 4;

    // Phase 1: all edge metadata
    int s[4], d[4], t[4];
    #pragma unroll
    for (int i = 0; i < 4; i++) {
        s[i] = __ldg(&src[ebase + i]);
        d[i] = __ldg(&dst[ebase + i]);
        t[i] = __ldg(&etype[ebase + i]);
    }
    float c0[4], c1[4];
    #pragma unroll
    for (int i = 0; i < 4; i++) {
        c0[i] = __ldg(&comp[t[i] * 2]);
        c1[i] = __ldg(&comp[t[i] * 2 + 1]);
    }

    // Phase 2: front-batch all 8 fp16 gathers (LDG.64 each)
    uint2 q0[4], q1[4];
    #pragma unroll
    for (int i = 0; i < 4; i++) {
        const uint2* p = (const uint2*)(g_proj + (size_t)s[i] * 128);
        q0[i] = __ldg(&p[lane]);        // basis 0: halfs [lane*4 .. lane*4+3]
        q1[i] = __ldg(&p[lane + 16]);   // basis 1: halfs [64+lane*4 ..]
    }

    // Phase 3: convert, mix, vector reduction
    #pragma unroll
    for (int i = 0; i < 4; i++) {
        float2 a0 = __half22float2(*(const __half2*)&q0[i].x);
        float2 a1 = __half22float2(*(const __half2*)&q0[i].y);
        float2 b0 = __half22float2(*(const __half2*)&q1[i].x);
        float2 b1 = __half22float2(*(const __half2*)&q1[i].y);

        float4 m;
        m.x = fmaf(c0[i], a0.x, c1[i] * b0.x);
        m.y = fmaf(c0[i], a0.y, c1[i] * b0.y);
        m.z = fmaf(c0[i], a1.x, c1[i] * b1.x);
        m.w = fmaf(c0[i], a1.y, c1[i] * b1.y);

        float* a = g_agg + (size_t)d[i] * HD + lane * 4;
        asm volatile("red.global.add.v4.f32 [%0], {%1, %2, %3, %4};"
                     :: "l"(a), "f"(m.x), "f"(m.y), "f"(m.z), "f"(m.w)
                     : "memory");
    }
}

// ---------------------------------------------------------------------------
// Final: sigmoid( sum(g_agg .* fc_w) + fc_b )
// ---------------------------------------------------------------------------
__global__ __launch_bounds__(256) void final_partial_kernel(
    const float* __restrict__ fcw)
{
    __shared__ float red[256];
    const int tid = threadIdx.x;
    const int total4 = NN * HD / 4;   // 800000 float4
    float s = 0.0f;
    for (int i = blockIdx.x * 256 + tid; i < total4; i += gridDim.x * 256) {
        float4 a = ((const float4*)g_agg)[i];
        float4 w = ((const float4*)fcw)[i];
        s += a.x * w.x + a.y * w.y + a.z * w.z + a.w * w.w;
    }
    red[tid] = s;
    __syncthreads();
    #pragma unroll
    for (int off = 128; off > 0; off >>= 1) {
        if (tid < off) red[tid] += red[tid + off];
        __syncthreads();
    }
    if (tid == 0) g_partial[blockIdx.x] = red[0];
}

__global__ void final_out_kernel(const float* __restrict__ fcb,
                                 float* __restrict__ out, int nparts)
{
    __shared__ float red[256];
    const int tid = threadIdx.x;
    float s = 0.0f;
    for (int i = tid; i < nparts; i += 256) s += g_partial[i];
    red[tid] = s;
    __syncthreads();
    #pragma unroll
    for (int off = 128; off > 0; off >>= 1) {
        if (tid < off) red[tid] += red[tid + off];
        __syncthreads();
    }
    if (tid == 0) {
        float v = red[0] + fcb[0];
        out[0] = 1.0f / (1.0f + expf(-v));
    }
}

// ---------------------------------------------------------------------------
extern "C" void kernel_launch(void* const* d_in, const int* in_sizes, int n_in,
                              void* d_out, int out_size)
{
    const float* features = (const float*)d_in[0];   // [50000,64]
    const float* V        = (const float*)d_in[1];   // [2,2,64,64]
    const float* comp     = (const float*)d_in[2];   // [2,8,2]
    const float* loop_w   = (const float*)d_in[3];   // [2,64,64]
    const float* bias     = (const float*)d_in[4];   // [2,64]
    const float* fc_w     = (const float*)d_in[5];   // [1, 50000*64]
    const float* fc_b     = (const float*)d_in[6];   // [1]
    const int*   src      = (const int*)d_in[7];     // [800000]
    const int*   dst      = (const int*)d_in[8];
    const int*   etype    = (const int*)d_in[9];
    float* out = (float*)d_out;

    const int smem_bytes = (64 * COLS + 64 * XS) * (int)sizeof(float); // 66560
    cudaFuncSetAttribute(node_gemm_kernel,
                         cudaFuncAttributeMaxDynamicSharedMemorySize, smem_bytes);

    const int gemm_blocks = (NN + TN - 1) / TN;   // 782
    const int edge_blocks = NE / 64;              // 12500

    // ---- layer 0 ----
    node_gemm_kernel<<<gemm_blocks, 256, smem_bytes>>>(
        features, V + 0 * 2 * 64 * 64, loop_w + 0 * 64 * 64, bias + 0 * 64, 0);
    edge_kernel<<<edge_blocks, 256>>>(src, dst, etype, comp + 0 * 16);

    // ---- layer 1 (x = relu(g_agg), read in-place inside node_gemm) ----
    node_gemm_kernel<<<gemm_blocks, 256, smem_bytes>>>(
        features /*unused*/, V + 1 * 2 * 64 * 64, loop_w + 1 * 64 * 64,
        bias + 1 * 64, 1);
    edge_kernel<<<edge_blocks, 256>>>(src, dst, etype, comp + 1 * 16);

    // ---- final dot + sigmoid ----
    const int red_blocks = 512;
    final_partial_kernel<<<red_blocks, 256>>>(fc_w);
    final_out_kernel<<<1, 256>>>(fc_b, out, red_blocks);
}

// round 15
// speedup vs baseline: 1.1259x; 1.0232x over previous
#include <cuda_runtime.h>
#include <cuda_fp16.h>
#include <math.h>

#define NN 50000
#define NE 800000
#define HD 64
#define COLS 192      // 2 bases * 64 + 64 loop cols
#define TN 64         // nodes per block in node GEMM
#define XS 68         // x smem row stride (floats), float4-aligned

typedef unsigned long long u64;

// Scratch (no allocations allowed)
__device__ __align__(16) __half g_proj[NN * 128];  // fp16: [n][b][o], b in {0,1}
__device__ __align__(16) float g_agg[NN * HD];     // aggregation / layer output
__device__ float g_partial[512];

// ---- packed f32x2 helpers (FFMA2 — PTX-only on sm_103a) ----------------
__device__ __forceinline__ u64 pack2(float lo, float hi) {
    u64 r; asm("mov.b64 %0, {%1, %2};" : "=l"(r) : "f"(lo), "f"(hi)); return r;
}
__device__ __forceinline__ void unpack2(u64 v, float& lo, float& hi) {
    asm("mov.b64 {%0, %1}, %2;" : "=f"(lo), "=f"(hi) : "l"(v));
}
__device__ __forceinline__ u64 fma2(u64 a, u64 b, u64 c) {
    u64 d; asm("fma.rn.f32x2 %0, %1, %2, %3;" : "=l"(d) : "l"(a), "l"(b), "l"(c));
    return d;
}

// ---------------------------------------------------------------------------
// Node GEMM: cols 0:128 -> g_proj (fp16), cols 128:192 -> g_agg = x@loop_w+bias
// x source: layer0 = features input; layer1 = relu(g_agg) read in-place.
// Block: 64 nodes x 192 cols, 256 threads, thread tile 4 nodes x 12 cols,
// accumulated as 4x6 packed f32x2 pairs.
// ---------------------------------------------------------------------------
__global__ __launch_bounds__(256, 3) void node_gemm_kernel(
    const float* __restrict__ xin,     // features (used when from_agg==0)
    const float* __restrict__ V,       // [2,64,64] (b,i,o) for this layer
    const float* __restrict__ loopw,   // [64,64] for this layer
    const float* __restrict__ bias,    // [64] for this layer
    int from_agg)
{
    extern __shared__ float sm[];
    float* Wsh = sm;                 // [64][192]
    float* Xsh = sm + 64 * COLS;     // [64][XS]

    const int tid = threadIdx.x;
    const int n0 = blockIdx.x * TN;

    // Load weights into smem: Wsh[k][c]
    for (int idx = tid; idx < 64 * COLS; idx += 256) {
        int k = idx / COLS, c = idx - k * COLS;
        float v;
        if (c < 128) {
            int b = c >> 6, o = c & 63;
            v = V[(b * 64 + k) * 64 + o];
        } else {
            v = loopw[k * 64 + (c - 128)];
        }
        Wsh[k * COLS + c] = v;
    }
    // Load x tile transposed: Xsh[k][n_local]
    for (int idx = tid; idx < TN * 64; idx += 256) {
        int nl = idx >> 6, k = idx & 63;
        int gn = n0 + nl;
        float v = 0.0f;
        if (gn < NN) {
            if (from_agg) {
                v = fmaxf(g_agg[gn * HD + k], 0.0f);
            } else {
                v = xin[gn * HD + k];
            }
        }
        Xsh[k * XS + nl] = v;
    }
    __syncthreads();

    const int cg = tid & 15;     // col group (12 cols = 6 pairs)
    const int ng = tid >> 4;     // node group (4 nodes)
    const int c0 = cg * 12;      // 48B*cg -> 16B aligned

    u64 acc[4][6];
    #pragma unroll
    for (int i = 0; i < 4; i++)
        #pragma unroll
        for (int j = 0; j < 6; j++) acc[i][j] = 0ULL;

    #pragma unroll 4
    for (int k = 0; k < 64; k++) {
        float4 xv = *(const float4*)&Xsh[k * XS + ng * 4];
        ulonglong2 wv0 = *(const ulonglong2*)&Wsh[k * COLS + c0];
        ulonglong2 wv1 = *(const ulonglong2*)&Wsh[k * COLS + c0 + 4];
        ulonglong2 wv2 = *(const ulonglong2*)&Wsh[k * COLS + c0 + 8];
        u64 w[6] = {wv0.x, wv0.y, wv1.x, wv1.y, wv2.x, wv2.y};
        u64 xx[4] = {pack2(xv.x, xv.x), pack2(xv.y, xv.y),
                     pack2(xv.z, xv.z), pack2(xv.w, xv.w)};
        #pragma unroll
        for (int i = 0; i < 4; i++)
            #pragma unroll
            for (int j = 0; j < 6; j++)
                acc[i][j] = fma2(xx[i], w[j], acc[i][j]);
    }

    // Store: cols < 128 -> g_proj (fp16 pairs); cols >= 128 -> g_agg (+bias)
    #pragma unroll
    for (int i = 0; i < 4; i++) {
        int gn = n0 + ng * 4 + i;
        if (gn >= NN) break;
        #pragma unroll
        for (int j = 0; j < 6; j++) {
            float lo, hi;
            unpack2(acc[i][j], lo, hi);
            int c = c0 + j * 2;
            if (c < 128) {
                *(__half2*)&g_proj[gn * 128 + c] = __floats2half2_rn(lo, hi);
            } else {
                g_agg[gn * HD + (c - 128)]     = lo + bias[c - 128];
                g_agg[gn * HD + (c - 128) + 1] = hi + bias[c - 127];
            }
        }
    }
}

// ---------------------------------------------------------------------------
// Edge scatter: msg = c0*proj[src,0,:] + c1*proj[src,1,:]; g_agg[dst] += msg
// Metadata staged through smem: threads 0-63 build a 16B struct per edge
// {src, dst, c0, c1} from coalesced loads; consumer groups read it back with
// a single broadcast LDS.128 per edge (was 20 redundant broadcast LDGs/warp).
// Gather: fp16 proj, 2x LDG.64 per lane, front-batched (MLP=8).
// Scatter: red.global.add.v4.f32 (fp32 accumulation preserved).
// ---------------------------------------------------------------------------
__global__ __launch_bounds__(256, 4) void edge_kernel(
    const int* __restrict__ src, const int* __restrict__ dst,
    const int* __restrict__ etype,
    const float* __restrict__ comp)   // [8][2] for this layer
{
    __shared__ float4 meta[64];       // {src bits, dst bits, c0, c1}

    const int tid = threadIdx.x;
    const int ebase = blockIdx.x * 64;

    if (tid < 64) {
        int e = ebase + tid;
        int s = __ldg(&src[e]);
        int d = __ldg(&dst[e]);
        int t = __ldg(&etype[e]);
        float c0 = __ldg(&comp[t * 2]);
        float c1 = __ldg(&comp[t * 2 + 1]);
        meta[tid] = make_float4(__int_as_float(s), __int_as_float(d), c0, c1);
    }
    __syncthreads();

    const int grp = tid >> 4;
    const int lane = tid & 15;

    // Phase 1: metadata via broadcast LDS.128
    float4 md[4];
    #pragma unroll
    for (int i = 0; i < 4; i++) md[i] = meta[grp * 4 + i];

    // Phase 2: front-batch all 8 fp16 gathers (LDG.64 each)
    uint2 q0[4], q1[4];
    #pragma unroll
    for (int i = 0; i < 4; i++) {
        int s = __float_as_int(md[i].x);
        const uint2* p = (const uint2*)(g_proj + (size_t)s * 128);
        q0[i] = __ldg(&p[lane]);        // basis 0
        q1[i] = __ldg(&p[lane + 16]);   // basis 1
    }

    // Phase 3: convert, mix, vector reduction
    #pragma unroll
    for (int i = 0; i < 4; i++) {
        float c0 = md[i].z, c1 = md[i].w;
        float2 a0 = __half22float2(*(const __half2*)&q0[i].x);
        float2 a1 = __half22float2(*(const __half2*)&q0[i].y);
        float2 b0 = __half22float2(*(const __half2*)&q1[i].x);
        float2 b1 = __half22float2(*(const __half2*)&q1[i].y);

        float4 m;
        m.x = fmaf(c0, a0.x, c1 * b0.x);
        m.y = fmaf(c0, a0.y, c1 * b0.y);
        m.z = fmaf(c0, a1.x, c1 * b1.x);
        m.w = fmaf(c0, a1.y, c1 * b1.y);

        int d = __float_as_int(md[i].y);
        float* a = g_agg + (size_t)d * HD + lane * 4;
        asm volatile("red.global.add.v4.f32 [%0], {%1, %2, %3, %4};"
                     :: "l"(a), "f"(m.x), "f"(m.y), "f"(m.z), "f"(m.w)
                     : "memory");
    }
}

// ---------------------------------------------------------------------------
// Final: sigmoid( sum(g_agg .* fc_w) + fc_b )
// ---------------------------------------------------------------------------
__global__ __launch_bounds__(256) void final_partial_kernel(
    const float* __restrict__ fcw)
{
    __shared__ float red[256];
    const int tid = threadIdx.x;
    const int total4 = NN * HD / 4;   // 800000 float4
    float s = 0.0f;
    for (int i = blockIdx.x * 256 + tid; i < total4; i += gridDim.x * 256) {
        float4 a = ((const float4*)g_agg)[i];
        float4 w = ((const float4*)fcw)[i];
        s += a.x * w.x + a.y * w.y + a.z * w.z + a.w * w.w;
    }
    red[tid] = s;
    __syncthreads();
    #pragma unroll
    for (int off = 128; off > 0; off >>= 1) {
        if (tid < off) red[tid] += red[tid + off];
        __syncthreads();
    }
    if (tid == 0) g_partial[blockIdx.x] = red[0];
}

__global__ void final_out_kernel(const float* __restrict__ fcb,
                                 float* __restrict__ out, int nparts)
{
    __shared__ float red[256];
    const int tid = threadIdx.x;
    float s = 0.0f;
    for (int i = tid; i < nparts; i += 256) s += g_partial[i];
    red[tid] = s;
    __syncthreads();
    #pragma unroll
    for (int off = 128; off > 0; off >>= 1) {
        if (tid < off) red[tid] += red[tid + off];
        __syncthreads();
    }
    if (tid == 0) {
        float v = red[0] + fcb[0];
        out[0] = 1.0f / (1.0f + expf(-v));
    }
}

// ---------------------------------------------------------------------------
extern "C" void kernel_launch(void* const* d_in, const int* in_sizes, int n_in,
                              void* d_out, int out_size)
{
    const float* features = (const float*)d_in[0];   // [50000,64]
    const float* V        = (const float*)d_in[1];   // [2,2,64,64]
    const float* comp     = (const float*)d_in[2];   // [2,8,2]
    const float* loop_w   = (const float*)d_in[3];   // [2,64,64]
    const float* bias     = (const float*)d_in[4];   // [2,64]
    const float* fc_w     = (const float*)d_in[5];   // [1, 50000*64]
    const float* fc_b     = (const float*)d_in[6];   // [1]
    const int*   src      = (const int*)d_in[7];     // [800000]
    const int*   dst      = (const int*)d_in[8];
    const int*   etype    = (const int*)d_in[9];
    float* out = (float*)d_out;

    const int smem_bytes = (64 * COLS + 64 * XS) * (int)sizeof(float); // 66560
    cudaFuncSetAttribute(node_gemm_kernel,
                         cudaFuncAttributeMaxDynamicSharedMemorySize, smem_bytes);

    const int gemm_blocks = (NN + TN - 1) / TN;   // 782
    const int edge_blocks = NE / 64;              // 12500

    // ---- layer 0 ----
    node_gemm_kernel<<<gemm_blocks, 256, smem_bytes>>>(
        features, V + 0 * 2 * 64 * 64, loop_w + 0 * 64 * 64, bias + 0 * 64, 0);
    edge_kernel<<<edge_blocks, 256>>>(src, dst, etype, comp + 0 * 16);

    // ---- layer 1 (x = relu(g_agg), read in-place inside node_gemm) ----
    node_gemm_kernel<<<gemm_blocks, 256, smem_bytes>>>(
        features /*unused*/, V + 1 * 2 * 64 * 64, loop_w + 1 * 64 * 64,
        bias + 1 * 64, 1);
    edge_kernel<<<edge_blocks, 256>>>(src, dst, etype, comp + 1 * 16);

    // ---- final dot + sigmoid ----
    const int red_blocks = 512;
    final_partial_kernel<<<red_blocks, 256>>>(fc_w);
    final_out_kernel<<<1, 256>>>(fc_b, out, red_blocks);
}